// round 11
// baseline (speedup 1.0000x reference)
#include <cuda_runtime.h>
#include <math.h>

#define N_RAYS    65536
#define N_SAMPLES 192
#define WARPS_PER_BLOCK 8
#define THREADS   (WARPS_PER_BLOCK * 32)
#define FULL      0xffffffffu

// Output layout (flattened tuple, reference order):
//   rgb_map | depth | acc | weights | disp | trans | alpha
// Ownership: pass A = samples 4l..4l+3 (0..127, float4); pass B = 128+2l..+1 (float2)

__global__ __launch_bounds__(THREADS, 8)
void nerf_render_kernel(const float* __restrict__ rgb,
                        const float* __restrict__ sigma,
                        const float* __restrict__ z_vals,
                        const float* __restrict__ rays_d,
                        float* __restrict__ out)
{
    __shared__ __align__(16) float srgb[WARPS_PER_BLOCK][N_SAMPLES * 3];
    __shared__ float sres[WARPS_PER_BLOCK][6];   // sr, sg, sb, depth, acc, disp

    const int warp = threadIdx.x >> 5;
    const int lane = threadIdx.x & 31;
    const int ray  = blockIdx.x * WARPS_PER_BLOCK + warp;
    const int rowbase = ray * N_SAMPLES;

    float* __restrict__ out_rgbm = out;
    float* __restrict__ out_dep  = out + 3 * N_RAYS;
    float* __restrict__ out_acc  = out + 4 * N_RAYS;
    float* __restrict__ out_w    = out + 5 * N_RAYS;
    float* __restrict__ out_disp = out + 5 * N_RAYS + (size_t)N_RAYS * N_SAMPLES;
    float* __restrict__ out_t    = out + 6 * N_RAYS + (size_t)N_RAYS * N_SAMPLES;
    float* __restrict__ out_a    = out + 6 * N_RAYS + 2 * (size_t)N_RAYS * N_SAMPLES;

    // ---- front-batched loads: rays_d first (feeds norm -> all dists) ----
    const float dx = __ldg(&rays_d[ray * 3 + 0]);
    const float dy = __ldg(&rays_d[ray * 3 + 1]);
    const float dz = __ldg(&rays_d[ray * 3 + 2]);

    const float4 zA  = __ldcs(((const float4*)(z_vals + rowbase)) + lane);
    const float2 zB  = __ldcs(((const float2*)(z_vals + rowbase + 128)) + lane);
    const float4 sgA = __ldcs(((const float4*)(sigma  + rowbase)) + lane);
    const float2 sgB = __ldcs(((const float2*)(sigma  + rowbase + 128)) + lane);

    {   // rgb row (576 floats) -> smem
        const float* __restrict__ rowp = rgb + (size_t)ray * (N_SAMPLES * 3);
        const float4* __restrict__ row4 = (const float4*)rowp;
#pragma unroll
        for (int k = 0; k < 4; ++k) {
            const int e = lane + 32 * k;
            *(float4*)&srgb[warp][e * 4] = __ldcs(&row4[e]);
        }
        *(float2*)&srgb[warp][512 + lane * 2] = __ldcs(((const float2*)(rowp + 512)) + lane);
    }

    const float norm = sqrtf(dx * dx + dy * dy + dz * dz);

    // ---- dists ----
    const float zA_next = __shfl_down_sync(FULL, zA.x, 1);
    const float zB0     = __shfl_sync(FULL, zB.x, 0);
    const float zB_next = __shfl_down_sync(FULL, zB.x, 1);

    const float dA0 = (zA.y - zA.x) * norm;
    const float dA1 = (zA.z - zA.y) * norm;
    const float dA2 = (zA.w - zA.z) * norm;
    const float dA3 = (((lane == 31) ? zB0 : zA_next) - zA.w) * norm;
    const float dB0 = (zB.y - zB.x) * norm;
    const float dB1 = (lane == 31) ? (1e10f * norm) : ((zB_next - zB.y) * norm);

    // ---- 1 - alpha ----
    const float omA0 = __expf(-fmaxf(sgA.x, 0.0f) * dA0);
    const float omA1 = __expf(-fmaxf(sgA.y, 0.0f) * dA1);
    const float omA2 = __expf(-fmaxf(sgA.z, 0.0f) * dA2);
    const float omA3 = __expf(-fmaxf(sgA.w, 0.0f) * dA3);
    const float omB0 = __expf(-fmaxf(sgB.x, 0.0f) * dB0);
    const float omB1 = __expf(-fmaxf(sgB.y, 0.0f) * dB1);

    // ---- alpha stores early (streaming; independent of the scan) ----
    __stcs(((float4*)(out_a + rowbase)) + lane,
           make_float4(1.0f - omA0, 1.0f - omA1, 1.0f - omA2, 1.0f - omA3));
    __stcs(((float2*)(out_a + rowbase + 128)) + lane, make_float2(1.0f - omB0, 1.0f - omB1));

    // ---- warp product scans: pass A lane product, pass B lane product (ILP) ----
    float inclA = omA0 * omA1 * omA2 * omA3;
    float inclB = omB0 * omB1;
#pragma unroll
    for (int off = 1; off < 32; off <<= 1) {
        const float vA = __shfl_up_sync(FULL, inclA, off);
        const float vB = __shfl_up_sync(FULL, inclB, off);
        if (lane >= off) { inclA *= vA; inclB *= vB; }
    }
    float exclA = __shfl_up_sync(FULL, inclA, 1);
    float exclB = __shfl_up_sync(FULL, inclB, 1);
    if (lane == 0) { exclA = 1.0f; exclB = 1.0f; }
    exclB *= __shfl_sync(FULL, inclA, 31);               // carry: prod over samples 0..127

    // ---- transmittance; store immediately ----
    const float tA0 = exclA;
    const float tA1 = tA0 * omA0;
    const float tA2 = tA1 * omA1;
    const float tA3 = tA2 * omA2;
    const float tB0 = exclB;
    const float tB1 = tB0 * omB0;

    __stcs(((float4*)(out_t + rowbase)) + lane, make_float4(tA0, tA1, tA2, tA3));
    __stcs(((float2*)(out_t + rowbase + 128)) + lane, make_float2(tB0, tB1));

    // ---- weights; store immediately ----
    const float wA0 = (1.0f - omA0) * tA0;
    const float wA1 = (1.0f - omA1) * tA1;
    const float wA2 = (1.0f - omA2) * tA2;
    const float wA3 = (1.0f - omA3) * tA3;
    const float wB0 = (1.0f - omB0) * tB0;
    const float wB1 = (1.0f - omB1) * tB1;

    __stcs(((float4*)(out_w + rowbase)) + lane, make_float4(wA0, wA1, wA2, wA3));
    __stcs(((float2*)(out_w + rowbase + 128)) + lane, make_float2(wB0, wB1));

    // ---- per-ray reductions ----
    float sw  = wA0 + wA1 + wA2 + wA3 + wB0 + wB1;
    float swz = wA0 * zA.x + wA1 * zA.y + wA2 * zA.z + wA3 * zA.w
              + wB0 * zB.x + wB1 * zB.y;

    __syncwarp();   // srgb visible across lanes

    // pass A rgb: floats 12l..12l+11 -> 3x LDS.128 (48B stride: conflict-free)
    const float4 q0 = *(const float4*)&srgb[warp][12 * lane + 0];
    const float4 q1 = *(const float4*)&srgb[warp][12 * lane + 4];
    const float4 q2 = *(const float4*)&srgb[warp][12 * lane + 8];
    // pass B rgb: floats 384+6l..+5 -> 3x LDS.64 (24B stride: conflict-free)
    const float2 f0 = *(const float2*)&srgb[warp][384 + 6 * lane + 0];
    const float2 f1 = *(const float2*)&srgb[warp][384 + 6 * lane + 2];
    const float2 f2 = *(const float2*)&srgb[warp][384 + 6 * lane + 4];

    float sr  = wA0 * q0.x + wA1 * q0.w + wA2 * q1.z + wA3 * q2.y + wB0 * f0.x + wB1 * f1.y;
    float sgc = wA0 * q0.y + wA1 * q1.x + wA2 * q1.w + wA3 * q2.z + wB0 * f0.y + wB1 * f2.x;
    float sb  = wA0 * q0.z + wA1 * q1.y + wA2 * q2.x + wA3 * q2.w + wB0 * f1.x + wB1 * f2.y;

#pragma unroll
    for (int off = 16; off >= 1; off >>= 1) {
        sw  += __shfl_xor_sync(FULL, sw,  off);
        swz += __shfl_xor_sync(FULL, swz, off);
        sr  += __shfl_xor_sync(FULL, sr,  off);
        sgc += __shfl_xor_sync(FULL, sgc, off);
        sb  += __shfl_xor_sync(FULL, sb,  off);
    }

    // ---- block-aggregated coalesced epilogue stores (8 rays/CTA) ----
    if (lane == 0) {
        sres[warp][0] = sr;
        sres[warp][1] = sgc;
        sres[warp][2] = sb;
        sres[warp][3] = swz;
        sres[warp][4] = sw;
        sres[warp][5] = 1.0f / fmaxf(1e-10f, swz / sw);
    }
    __syncthreads();

    const int tid = threadIdx.x;
    const int r0  = blockIdx.x * WARPS_PER_BLOCK;
    if (tid < 24) {                                  // rgb_map: 24 contiguous floats
        out_rgbm[r0 * 3 + tid] = sres[tid / 3][tid % 3];
    } else if (tid < 32) {                           // depth: 8 contiguous floats
        out_dep[r0 + tid - 24] = sres[tid - 24][3];
    } else if (tid < 40) {                           // acc
        out_acc[r0 + tid - 32] = sres[tid - 32][4];
    } else if (tid < 48) {                           // disp
        out_disp[r0 + tid - 40] = sres[tid - 40][5];
    }
}

extern "C" void kernel_launch(void* const* d_in, const int* in_sizes, int n_in,
                              void* d_out, int out_size)
{
    const float* rgb    = (const float*)d_in[0];
    const float* sigma  = (const float*)d_in[1];
    const float* z_vals = (const float*)d_in[2];
    const float* rays_d = (const float*)d_in[3];
    float* out = (float*)d_out;

    nerf_render_kernel<<<N_RAYS / WARPS_PER_BLOCK, THREADS>>>(rgb, sigma, z_vals, rays_d, out);
}

// round 12
// speedup vs baseline: 1.1077x; 1.1077x over previous
#include <cuda_runtime.h>
#include <math.h>

#define N_RAYS    65536
#define N_SAMPLES 192
#define WARPS_PER_BLOCK 4
#define THREADS   (WARPS_PER_BLOCK * 32)
#define FULL      0xffffffffu

// Output layout (flattened tuple, reference order):
//   rgb_map | depth | acc | weights | disp | trans | alpha
// Ownership: pass A = samples 4l..4l+3 (0..127, float4); pass B = 128+2l..+1 (float2)

__global__ __launch_bounds__(THREADS, 16)
void nerf_render_kernel(const float* __restrict__ rgb,
                        const float* __restrict__ sigma,
                        const float* __restrict__ z_vals,
                        const float* __restrict__ rays_d,
                        float* __restrict__ out)
{
    __shared__ __align__(16) float srgb[WARPS_PER_BLOCK][N_SAMPLES * 3];
    __shared__ float sres[WARPS_PER_BLOCK][6];   // sr, sg, sb, depth, acc, disp

    const int warp = threadIdx.x >> 5;
    const int lane = threadIdx.x & 31;
    const int ray  = blockIdx.x * WARPS_PER_BLOCK + warp;
    const int rowbase = ray * N_SAMPLES;

    float* __restrict__ out_rgbm = out;
    float* __restrict__ out_dep  = out + 3 * N_RAYS;
    float* __restrict__ out_acc  = out + 4 * N_RAYS;
    float* __restrict__ out_w    = out + 5 * N_RAYS;
    float* __restrict__ out_disp = out + 5 * N_RAYS + (size_t)N_RAYS * N_SAMPLES;
    float* __restrict__ out_t    = out + 6 * N_RAYS + (size_t)N_RAYS * N_SAMPLES;
    float* __restrict__ out_a    = out + 6 * N_RAYS + 2 * (size_t)N_RAYS * N_SAMPLES;

    // ---- front-batched loads: rays_d first (feeds norm -> all dists) ----
    const float dx = __ldg(&rays_d[ray * 3 + 0]);
    const float dy = __ldg(&rays_d[ray * 3 + 1]);
    const float dz = __ldg(&rays_d[ray * 3 + 2]);

    const float4 zA  = __ldcs(((const float4*)(z_vals + rowbase)) + lane);
    const float2 zB  = __ldcs(((const float2*)(z_vals + rowbase + 128)) + lane);
    const float4 sgA = __ldcs(((const float4*)(sigma  + rowbase)) + lane);
    const float2 sgB = __ldcs(((const float2*)(sigma  + rowbase + 128)) + lane);

    {   // rgb row (576 floats) -> smem
        const float* __restrict__ rowp = rgb + (size_t)ray * (N_SAMPLES * 3);
        const float4* __restrict__ row4 = (const float4*)rowp;
#pragma unroll
        for (int k = 0; k < 4; ++k) {
            const int e = lane + 32 * k;
            *(float4*)&srgb[warp][e * 4] = __ldcs(&row4[e]);
        }
        *(float2*)&srgb[warp][512 + lane * 2] = __ldcs(((const float2*)(rowp + 512)) + lane);
    }

    const float norm = sqrtf(dx * dx + dy * dy + dz * dz);

    // ---- dists ----
    const float zA_next = __shfl_down_sync(FULL, zA.x, 1);
    const float zB0     = __shfl_sync(FULL, zB.x, 0);
    const float zB_next = __shfl_down_sync(FULL, zB.x, 1);

    const float dA0 = (zA.y - zA.x) * norm;
    const float dA1 = (zA.z - zA.y) * norm;
    const float dA2 = (zA.w - zA.z) * norm;
    const float dA3 = (((lane == 31) ? zB0 : zA_next) - zA.w) * norm;
    const float dB0 = (zB.y - zB.x) * norm;
    const float dB1 = (lane == 31) ? (1e10f * norm) : ((zB_next - zB.y) * norm);

    // ---- 1 - alpha ----
    const float omA0 = __expf(-fmaxf(sgA.x, 0.0f) * dA0);
    const float omA1 = __expf(-fmaxf(sgA.y, 0.0f) * dA1);
    const float omA2 = __expf(-fmaxf(sgA.z, 0.0f) * dA2);
    const float omA3 = __expf(-fmaxf(sgA.w, 0.0f) * dA3);
    const float omB0 = __expf(-fmaxf(sgB.x, 0.0f) * dB0);
    const float omB1 = __expf(-fmaxf(sgB.y, 0.0f) * dB1);

    // ---- alpha stores early (streaming; independent of the scan) ----
    __stcs(((float4*)(out_a + rowbase)) + lane,
           make_float4(1.0f - omA0, 1.0f - omA1, 1.0f - omA2, 1.0f - omA3));
    __stcs(((float2*)(out_a + rowbase + 128)) + lane, make_float2(1.0f - omB0, 1.0f - omB1));

    // ---- warp product scans: pass A lane product, pass B lane product (ILP) ----
    float inclA = omA0 * omA1 * omA2 * omA3;
    float inclB = omB0 * omB1;
#pragma unroll
    for (int off = 1; off < 32; off <<= 1) {
        const float vA = __shfl_up_sync(FULL, inclA, off);
        const float vB = __shfl_up_sync(FULL, inclB, off);
        if (lane >= off) { inclA *= vA; inclB *= vB; }
    }
    float exclA = __shfl_up_sync(FULL, inclA, 1);
    float exclB = __shfl_up_sync(FULL, inclB, 1);
    if (lane == 0) { exclA = 1.0f; exclB = 1.0f; }
    exclB *= __shfl_sync(FULL, inclA, 31);               // carry: prod over samples 0..127

    // ---- transmittance; store immediately ----
    const float tA0 = exclA;
    const float tA1 = tA0 * omA0;
    const float tA2 = tA1 * omA1;
    const float tA3 = tA2 * omA2;
    const float tB0 = exclB;
    const float tB1 = tB0 * omB0;

    __stcs(((float4*)(out_t + rowbase)) + lane, make_float4(tA0, tA1, tA2, tA3));
    __stcs(((float2*)(out_t + rowbase + 128)) + lane, make_float2(tB0, tB1));

    // ---- weights; store immediately ----
    const float wA0 = (1.0f - omA0) * tA0;
    const float wA1 = (1.0f - omA1) * tA1;
    const float wA2 = (1.0f - omA2) * tA2;
    const float wA3 = (1.0f - omA3) * tA3;
    const float wB0 = (1.0f - omB0) * tB0;
    const float wB1 = (1.0f - omB1) * tB1;

    __stcs(((float4*)(out_w + rowbase)) + lane, make_float4(wA0, wA1, wA2, wA3));
    __stcs(((float2*)(out_w + rowbase + 128)) + lane, make_float2(wB0, wB1));

    // ---- per-ray reductions ----
    float sw  = wA0 + wA1 + wA2 + wA3 + wB0 + wB1;
    float swz = wA0 * zA.x + wA1 * zA.y + wA2 * zA.z + wA3 * zA.w
              + wB0 * zB.x + wB1 * zB.y;

    __syncwarp();   // srgb visible across lanes

    // pass A rgb: floats 12l..12l+11 -> 3x LDS.128 (48B stride: conflict-free)
    const float4 q0 = *(const float4*)&srgb[warp][12 * lane + 0];
    const float4 q1 = *(const float4*)&srgb[warp][12 * lane + 4];
    const float4 q2 = *(const float4*)&srgb[warp][12 * lane + 8];
    // pass B rgb: floats 384+6l..+5 -> 3x LDS.64 (24B stride: conflict-free)
    const float2 f0 = *(const float2*)&srgb[warp][384 + 6 * lane + 0];
    const float2 f1 = *(const float2*)&srgb[warp][384 + 6 * lane + 2];
    const float2 f2 = *(const float2*)&srgb[warp][384 + 6 * lane + 4];

    float sr  = wA0 * q0.x + wA1 * q0.w + wA2 * q1.z + wA3 * q2.y + wB0 * f0.x + wB1 * f1.y;
    float sgc = wA0 * q0.y + wA1 * q1.x + wA2 * q1.w + wA3 * q2.z + wB0 * f0.y + wB1 * f2.x;
    float sb  = wA0 * q0.z + wA1 * q1.y + wA2 * q2.x + wA3 * q2.w + wB0 * f1.x + wB1 * f2.y;

#pragma unroll
    for (int off = 16; off >= 1; off >>= 1) {
        sw  += __shfl_xor_sync(FULL, sw,  off);
        swz += __shfl_xor_sync(FULL, swz, off);
        sr  += __shfl_xor_sync(FULL, sr,  off);
        sgc += __shfl_xor_sync(FULL, sgc, off);
        sb  += __shfl_xor_sync(FULL, sb,  off);
    }

    // ---- block-aggregated coalesced epilogue stores ----
    if (lane == 0) {
        sres[warp][0] = sr;
        sres[warp][1] = sgc;
        sres[warp][2] = sb;
        sres[warp][3] = swz;
        sres[warp][4] = sw;
        sres[warp][5] = 1.0f / fmaxf(1e-10f, swz / sw);
    }
    __syncthreads();

    const int tid = threadIdx.x;
    const int r0  = blockIdx.x * WARPS_PER_BLOCK;
    if (tid < 12) {                                  // rgb_map: 12 contiguous floats
        out_rgbm[r0 * 3 + tid] = sres[tid / 3][tid % 3];
    } else if (tid < 16) {                           // depth
        out_dep[r0 + tid - 12] = sres[tid - 12][3];
    } else if (tid < 20) {                           // acc
        out_acc[r0 + tid - 16] = sres[tid - 16][4];
    } else if (tid < 24) {                           // disp
        out_disp[r0 + tid - 20] = sres[tid - 20][5];
    }
}

extern "C" void kernel_launch(void* const* d_in, const int* in_sizes, int n_in,
                              void* d_out, int out_size)
{
    const float* rgb    = (const float*)d_in[0];
    const float* sigma  = (const float*)d_in[1];
    const float* z_vals = (const float*)d_in[2];
    const float* rays_d = (const float*)d_in[3];
    float* out = (float*)d_out;

    nerf_render_kernel<<<N_RAYS / WARPS_PER_BLOCK, THREADS>>>(rgb, sigma, z_vals, rays_d, out);
}